// round 1
// baseline (speedup 1.0000x reference)
#include <cuda_runtime.h>
#include <math.h>

// ---------------------------------------------------------------------------
// Dims
// ---------------------------------------------------------------------------
#define BB 64
// stage1: imgs [64,3,224,224] -> dynconv 7x7 s2 p3 -> [64,64,112,112] -> bn -> pool -> [64,64,56,56]
// stage2: dynconv 3x3 s2 p1 -> [64,128,28,28] -> bn -> pool -> [64,128,14,14]
// res:    conv3x3 s2 -> [64,256,7,7]; conv3x3 s1; shortcut 1x1 s2; relu(l+r)
// tail:   y = mean_hw; out = y @ (fc_w@wo@wv)^T + (fc_w@bo + fc_b)

// ---------------------------------------------------------------------------
// Scratch (device globals; no allocation allowed)
// ---------------------------------------------------------------------------
__device__ float g_pooled1[BB * 3];
__device__ float g_attn1[BB * 8];
__device__ float g_w1[BB * 64 * 3 * 49];         // 602,112
__device__ float g_conv1[BB * 64 * 112 * 112];   // 51,380,224
__device__ float g_pool1[BB * 64 * 56 * 56];     // 12,845,056
__device__ float g_pooled2[BB * 64];             // accumulated sums (zeroed)
__device__ float g_attn2[BB * 8];
__device__ float g_w2[BB * 128 * 64 * 9];        // 4,718,592
__device__ float g_conv2[BB * 128 * 28 * 28];    // 6,422,528
__device__ float g_pool2[BB * 128 * 14 * 14];    // 1,605,632
__device__ float g_rc1[BB * 256 * 49];           // 802,816
__device__ float g_rc2[BB * 256 * 49];
__device__ float g_rs[BB * 256 * 49];
__device__ float g_y[BB * 256];

// bn stats / scale-shift per stage
__device__ float g_sum1[64],  g_sq1[64],  g_sc1[64],  g_sh1[64];
__device__ float g_sum2[128], g_sq2[128], g_sc2[128], g_sh2[128];
__device__ float g_sumr1[256], g_sqr1[256], g_scr1[256], g_shr1[256];
__device__ float g_sumr2[256], g_sqr2[256], g_scr2[256], g_shr2[256];
__device__ float g_sums[256],  g_sqs[256],  g_scs[256],  g_shs[256];

// folded tail matrices
__device__ float g_T[50 * 1024];
__device__ float g_M[50 * 256];
__device__ float g_b2[50];

// ---------------------------------------------------------------------------
// Utilities
// ---------------------------------------------------------------------------
__global__ void k_zero() {
    int i = blockIdx.x * blockDim.x + threadIdx.x;
    if (i < 64)  { g_sum1[i] = 0.f; g_sq1[i] = 0.f; }
    if (i < 128) { g_sum2[i] = 0.f; g_sq2[i] = 0.f; }
    if (i < 256) {
        g_sumr1[i] = 0.f; g_sqr1[i] = 0.f;
        g_sumr2[i] = 0.f; g_sqr2[i] = 0.f;
        g_sums[i]  = 0.f; g_sqs[i]  = 0.f;
    }
    if (i < BB * 64) g_pooled2[i] = 0.f;
}

// stage: 0=bn1 1=bn2 2=res_bn1 3=res_bn2 4=res_bns
__global__ void k_bnscale(const float* __restrict__ g, const float* __restrict__ be,
                          float cnt, int stage, int C) {
    int c = blockIdx.x * blockDim.x + threadIdx.x;
    if (c >= C) return;
    float *su, *sq, *sc, *sh;
    switch (stage) {
        case 0:  su = g_sum1;  sq = g_sq1;  sc = g_sc1;  sh = g_sh1;  break;
        case 1:  su = g_sum2;  sq = g_sq2;  sc = g_sc2;  sh = g_sh2;  break;
        case 2:  su = g_sumr1; sq = g_sqr1; sc = g_scr1; sh = g_shr1; break;
        case 3:  su = g_sumr2; sq = g_sqr2; sc = g_scr2; sh = g_shr2; break;
        default: su = g_sums;  sq = g_sqs;  sc = g_scs;  sh = g_shs;  break;
    }
    float m = su[c] / cnt;
    float v = sq[c] / cnt - m * m;
    float s = g[c] * rsqrtf(v + 1e-5f);
    sc[c] = s;
    sh[c] = be[c] - m * s;
}

// ---------------------------------------------------------------------------
// Stage 1 attention + dynamic weights
// ---------------------------------------------------------------------------
__global__ void k_pooled1(const float* __restrict__ imgs) {
    int bc = blockIdx.x;                 // 192 = 64*3
    int tid = threadIdx.x;
    const float* p = imgs + (long)bc * 50176;
    float s = 0.f;
    for (int i = tid; i < 50176; i += 256) s += p[i];
    __shared__ float red[256];
    red[tid] = s; __syncthreads();
    for (int o = 128; o; o >>= 1) { if (tid < o) red[tid] += red[tid + o]; __syncthreads(); }
    if (tid == 0) g_pooled1[bc] = red[0] * (1.f / 50176.f);
}

__global__ void k_attn1(const float* __restrict__ fc1, const float* __restrict__ fc2,
                        const float* __restrict__ fc2b) {
    int b = threadIdx.x;
    if (b >= BB) return;
    float p[3];
    for (int c = 0; c < 3; c++) p[c] = g_pooled1[b * 3 + c];
    float h[8];
    for (int j = 0; j < 8; j++) {
        float s = 0.f;
        for (int c = 0; c < 3; c++) s += p[c] * fc1[j * 3 + c];
        h[j] = fmaxf(s, 0.f);
    }
    float lg[8], mx = -1e30f;
    for (int k = 0; k < 8; k++) {
        float s = fc2b[k];
        for (int j = 0; j < 8; j++) s += h[j] * fc2[k * 8 + j];
        lg[k] = s; mx = fmaxf(mx, s);
    }
    float den = 0.f;
    for (int k = 0; k < 8; k++) { lg[k] = expf(lg[k] - mx); den += lg[k]; }
    float inv = 1.f / den;
    for (int k = 0; k < 8; k++) g_attn1[b * 8 + k] = lg[k] * inv;
}

__global__ void k_w1agg(const float* __restrict__ dy1) {
    int idx = blockIdx.x * 256 + threadIdx.x;
    if (idx >= BB * 9408) return;
    int b = idx / 9408, i = idx - b * 9408;
    float s = 0.f;
#pragma unroll
    for (int k = 0; k < 8; k++) s += g_attn1[b * 8 + k] * dy1[k * 9408 + i];
    g_w1[idx] = s;
}

// ---------------------------------------------------------------------------
// Conv1: 3->64, 7x7 s2 p3, per-sample weights. Tile 16x16 outputs, 4 co/block.
// ---------------------------------------------------------------------------
__global__ void k_conv1(const float* __restrict__ imgs) {
    __shared__ float s_in[3 * 37 * 37];
    __shared__ float s_w[4 * 147];
    __shared__ float s_stat[8];
    int b = blockIdx.z, cog = blockIdx.y, tile = blockIdx.x;
    int tY = tile / 7, tX = tile - tY * 7;
    int tid = threadIdx.y * 16 + threadIdx.x;

    for (int t = tid; t < 588; t += 256)
        s_w[t] = g_w1[b * 9408 + cog * 588 + t];
    int ih0 = tY * 32 - 3, iw0 = tX * 32 - 3;
    for (int t = tid; t < 3 * 1369; t += 256) {
        int ci = t / 1369, rem = t - ci * 1369;
        int r = rem / 37, cc = rem - r * 37;
        int ih = ih0 + r, iw = iw0 + cc;
        float v = 0.f;
        if ((unsigned)ih < 224u && (unsigned)iw < 224u)
            v = imgs[((b * 3 + ci) * 224 + ih) * 224 + iw];
        s_in[t] = v;
    }
    if (tid < 8) s_stat[tid] = 0.f;
    __syncthreads();

    int ty = threadIdx.y, tx = threadIdx.x;
    float a0 = 0.f, a1 = 0.f, a2 = 0.f, a3 = 0.f;
    for (int ci = 0; ci < 3; ci++) {
        for (int kh = 0; kh < 7; kh++) {
            int ibase = ci * 1369 + (ty * 2 + kh) * 37 + tx * 2;
            int wbase = ci * 49 + kh * 7;
#pragma unroll
            for (int kw = 0; kw < 7; kw++) {
                float v = s_in[ibase + kw];
                a0 += s_w[wbase + kw] * v;
                a1 += s_w[147 + wbase + kw] * v;
                a2 += s_w[294 + wbase + kw] * v;
                a3 += s_w[441 + wbase + kw] * v;
            }
        }
    }
    int oh = tY * 16 + ty, ow = tX * 16 + tx;
    int base = ((b * 64 + cog * 4) * 112 + oh) * 112 + ow;
    g_conv1[base] = a0;
    g_conv1[base + 12544] = a1;
    g_conv1[base + 25088] = a2;
    g_conv1[base + 37632] = a3;

    float acc[4] = {a0, a1, a2, a3};
#pragma unroll
    for (int j = 0; j < 4; j++) {
        float s = acc[j], q = acc[j] * acc[j];
        for (int o = 16; o; o >>= 1) {
            s += __shfl_down_sync(0xffffffffu, s, o);
            q += __shfl_down_sync(0xffffffffu, q, o);
        }
        if ((tid & 31) == 0) { atomicAdd(&s_stat[j], s); atomicAdd(&s_stat[4 + j], q); }
    }
    __syncthreads();
    if (tid < 4) {
        atomicAdd(&g_sum1[cog * 4 + tid], s_stat[tid]);
        atomicAdd(&g_sq1[cog * 4 + tid], s_stat[4 + tid]);
    }
}

// ---------------------------------------------------------------------------
// BN1 + maxpool3 s2 p1: 112->56, plus accumulate pooled2 sums per (b,c)
// ---------------------------------------------------------------------------
__global__ void k_bnpool1() {
    int b = blockIdx.z, c = blockIdx.y;
    int p = blockIdx.x * 256 + threadIdx.x;
    float outv = 0.f;
    bool valid = (p < 3136);
    if (valid) {
        int oh = p / 56, ow = p - oh * 56;
        float sc = g_sc1[c], sh = g_sh1[c];
        const float* ip = g_conv1 + (b * 64 + c) * 12544;
        float m = -1e30f;
#pragma unroll
        for (int r = 0; r < 3; r++) {
            int ih = 2 * oh - 1 + r;
            if ((unsigned)ih >= 112u) continue;
#pragma unroll
            for (int cc = 0; cc < 3; cc++) {
                int iw = 2 * ow - 1 + cc;
                if ((unsigned)iw >= 112u) continue;
                float v = ip[ih * 112 + iw] * sc + sh;
                m = fmaxf(m, v);
            }
        }
        g_pool1[(b * 64 + c) * 3136 + p] = m;
        outv = m;
    }
    float s = valid ? outv : 0.f;
    for (int o = 16; o; o >>= 1) s += __shfl_down_sync(0xffffffffu, s, o);
    __shared__ float s_red;
    if (threadIdx.x == 0) s_red = 0.f;
    __syncthreads();
    if ((threadIdx.x & 31) == 0) atomicAdd(&s_red, s);
    __syncthreads();
    if (threadIdx.x == 0) atomicAdd(&g_pooled2[b * 64 + c], s_red);
}

// ---------------------------------------------------------------------------
// Stage 2 attention + dynamic weights
// ---------------------------------------------------------------------------
__global__ void k_attn2(const float* __restrict__ fc1, const float* __restrict__ fc2,
                        const float* __restrict__ fc2b) {
    int b = threadIdx.x;
    if (b >= BB) return;
    float h[17];
    for (int j = 0; j < 17; j++) {
        float s = 0.f;
        for (int c = 0; c < 64; c++)
            s += (g_pooled2[b * 64 + c] * (1.f / 3136.f)) * fc1[j * 64 + c];
        h[j] = fmaxf(s, 0.f);
    }
    float lg[8], mx = -1e30f;
    for (int k = 0; k < 8; k++) {
        float s = fc2b[k];
        for (int j = 0; j < 17; j++) s += h[j] * fc2[k * 17 + j];
        lg[k] = s; mx = fmaxf(mx, s);
    }
    float den = 0.f;
    for (int k = 0; k < 8; k++) { lg[k] = expf(lg[k] - mx); den += lg[k]; }
    float inv = 1.f / den;
    for (int k = 0; k < 8; k++) g_attn2[b * 8 + k] = lg[k] * inv;
}

__global__ void k_w2agg(const float* __restrict__ dy2) {
    int idx = blockIdx.x * 256 + threadIdx.x;
    if (idx >= BB * 73728) return;
    int b = idx / 73728, i = idx - b * 73728;
    float s = 0.f;
#pragma unroll
    for (int k = 0; k < 8; k++) s += g_attn2[b * 8 + k] * dy2[k * 73728 + i];
    g_w2[idx] = s;
}

// ---------------------------------------------------------------------------
// Conv2: 64->128, 3x3 s2 p1 on 56x56 -> 28x28, per-sample weights.
// 4 co/block, full 28x28 per block, ci chunks of 2 staged in smem.
// ---------------------------------------------------------------------------
__global__ void k_conv2() {
    __shared__ float s_in[2 * 3136];
    __shared__ float s_w[72];           // 4co * 2ci * 9
    __shared__ float s_stat[8];
    int b = blockIdx.y, cog = blockIdx.x;
    int tid = threadIdx.x;

    float acc[16];
#pragma unroll
    for (int i = 0; i < 16; i++) acc[i] = 0.f;
    if (tid < 8) s_stat[tid] = 0.f;

    int ohs[4], ows[4];
#pragma unroll
    for (int pi = 0; pi < 4; pi++) {
        int p = tid + pi * 256;
        ohs[pi] = p / 28; ows[pi] = p - ohs[pi] * 28;
    }

    for (int c0 = 0; c0 < 64; c0 += 2) {
        __syncthreads();
        for (int t = tid; t < 6272; t += 256) {
            int cl = t / 3136, pp = t - cl * 3136;
            s_in[t] = g_pool1[(b * 64 + c0 + cl) * 3136 + pp];
        }
        if (tid < 72) {
            int co = tid / 18, rr = tid - co * 18;
            int ci = rr / 9, r = rr - ci * 9;
            s_w[tid] = g_w2[b * 73728 + (cog * 4 + co) * 576 + (c0 + ci) * 9 + r];
        }
        __syncthreads();
#pragma unroll
        for (int ci = 0; ci < 2; ci++) {
#pragma unroll
            for (int kh = 0; kh < 3; kh++) {
#pragma unroll
                for (int kw = 0; kw < 3; kw++) {
                    int wi = ci * 9 + kh * 3 + kw;
                    float w0 = s_w[wi], w1 = s_w[18 + wi], w2 = s_w[36 + wi], w3 = s_w[54 + wi];
#pragma unroll
                    for (int pi = 0; pi < 4; pi++) {
                        int p = tid + pi * 256;
                        if (p >= 784) continue;
                        int ih = ohs[pi] * 2 - 1 + kh;
                        int iw = ows[pi] * 2 - 1 + kw;
                        float v = 0.f;
                        if ((unsigned)ih < 56u && (unsigned)iw < 56u)
                            v = s_in[ci * 3136 + ih * 56 + iw];
                        acc[pi * 4 + 0] += w0 * v;
                        acc[pi * 4 + 1] += w1 * v;
                        acc[pi * 4 + 2] += w2 * v;
                        acc[pi * 4 + 3] += w3 * v;
                    }
                }
            }
        }
    }

#pragma unroll
    for (int pi = 0; pi < 4; pi++) {
        int p = tid + pi * 256;
        if (p >= 784) continue;
#pragma unroll
        for (int co = 0; co < 4; co++)
            g_conv2[(b * 128 + cog * 4 + co) * 784 + p] = acc[pi * 4 + co];
    }
#pragma unroll
    for (int co = 0; co < 4; co++) {
        float s = 0.f, q = 0.f;
#pragma unroll
        for (int pi = 0; pi < 4; pi++) {
            int p = tid + pi * 256;
            if (p < 784) { float a = acc[pi * 4 + co]; s += a; q += a * a; }
        }
        for (int o = 16; o; o >>= 1) {
            s += __shfl_down_sync(0xffffffffu, s, o);
            q += __shfl_down_sync(0xffffffffu, q, o);
        }
        if ((tid & 31) == 0) { atomicAdd(&s_stat[co], s); atomicAdd(&s_stat[4 + co], q); }
    }
    __syncthreads();
    if (tid < 4) {
        atomicAdd(&g_sum2[cog * 4 + tid], s_stat[tid]);
        atomicAdd(&g_sq2[cog * 4 + tid], s_stat[4 + tid]);
    }
}

// ---------------------------------------------------------------------------
// BN2 + maxpool3 s2 p1: 28->14
// ---------------------------------------------------------------------------
__global__ void k_bnpool2() {
    int b = blockIdx.y, c = blockIdx.x;
    int p = threadIdx.x;           // 196 threads
    if (p >= 196) return;
    int oh = p / 14, ow = p - oh * 14;
    float sc = g_sc2[c], sh = g_sh2[c];
    const float* ip = g_conv2 + (b * 128 + c) * 784;
    float m = -1e30f;
#pragma unroll
    for (int r = 0; r < 3; r++) {
        int ih = 2 * oh - 1 + r;
        if ((unsigned)ih >= 28u) continue;
#pragma unroll
        for (int cc = 0; cc < 3; cc++) {
            int iw = 2 * ow - 1 + cc;
            if ((unsigned)iw >= 28u) continue;
            m = fmaxf(m, ip[ih * 28 + iw] * sc + sh);
        }
    }
    g_pool2[(b * 128 + c) * 196 + p] = m;
}

// ---------------------------------------------------------------------------
// Residual block
// ---------------------------------------------------------------------------
__global__ void k_resconv1(const float* __restrict__ w) {
    int b = blockIdx.y, co = blockIdx.x;
    int tid = threadIdx.x;               // 64 threads, 49 active
    float acc = 0.f;
    if (tid < 49) {
        int oh = tid / 7, ow = tid - oh * 7;
        const float* wb = w + co * 1152;
        for (int ci = 0; ci < 128; ci++) {
            const float* ip = g_pool2 + (b * 128 + ci) * 196;
            const float* wc = wb + ci * 9;
#pragma unroll
            for (int kh = 0; kh < 3; kh++) {
                int ih = oh * 2 - 1 + kh;
                if ((unsigned)ih >= 14u) continue;
#pragma unroll
                for (int kw = 0; kw < 3; kw++) {
                    int iw = ow * 2 - 1 + kw;
                    if ((unsigned)iw < 14u) acc += wc[kh * 3 + kw] * ip[ih * 14 + iw];
                }
            }
        }
        g_rc1[(b * 256 + co) * 49 + tid] = acc;
    }
    float s = (tid < 49) ? acc : 0.f, q = s * s;
    for (int o = 16; o; o >>= 1) {
        s += __shfl_down_sync(0xffffffffu, s, o);
        q += __shfl_down_sync(0xffffffffu, q, o);
    }
    __shared__ float s_s[2], s_q[2];
    if ((tid & 31) == 0) { s_s[tid >> 5] = s; s_q[tid >> 5] = q; }
    __syncthreads();
    if (tid == 0) {
        atomicAdd(&g_sumr1[co], s_s[0] + s_s[1]);
        atomicAdd(&g_sqr1[co], s_q[0] + s_q[1]);
    }
}

__global__ void k_bnrelu_rc1() {
    int idx = blockIdx.x * 256 + threadIdx.x;
    if (idx >= BB * 256 * 49) return;
    int c = (idx / 49) & 255;
    float v = g_rc1[idx] * g_scr1[c] + g_shr1[c];
    g_rc1[idx] = fmaxf(v, 0.f);
}

__global__ void k_resconv2(const float* __restrict__ w) {
    int b = blockIdx.y, co = blockIdx.x;
    int tid = threadIdx.x;
    float acc = 0.f;
    if (tid < 49) {
        int oh = tid / 7, ow = tid - oh * 7;
        const float* wb = w + co * 2304;
        for (int ci = 0; ci < 256; ci++) {
            const float* ip = g_rc1 + (b * 256 + ci) * 49;
            const float* wc = wb + ci * 9;
#pragma unroll
            for (int kh = 0; kh < 3; kh++) {
                int ih = oh - 1 + kh;
                if ((unsigned)ih >= 7u) continue;
#pragma unroll
                for (int kw = 0; kw < 3; kw++) {
                    int iw = ow - 1 + kw;
                    if ((unsigned)iw < 7u) acc += wc[kh * 3 + kw] * ip[ih * 7 + iw];
                }
            }
        }
        g_rc2[(b * 256 + co) * 49 + tid] = acc;
    }
    float s = (tid < 49) ? acc : 0.f, q = s * s;
    for (int o = 16; o; o >>= 1) {
        s += __shfl_down_sync(0xffffffffu, s, o);
        q += __shfl_down_sync(0xffffffffu, q, o);
    }
    __shared__ float s_s[2], s_q[2];
    if ((tid & 31) == 0) { s_s[tid >> 5] = s; s_q[tid >> 5] = q; }
    __syncthreads();
    if (tid == 0) {
        atomicAdd(&g_sumr2[co], s_s[0] + s_s[1]);
        atomicAdd(&g_sqr2[co], s_q[0] + s_q[1]);
    }
}

__global__ void k_shortcut(const float* __restrict__ w) {
    int b = blockIdx.y, co = blockIdx.x;
    int tid = threadIdx.x;
    float acc = 0.f;
    if (tid < 49) {
        int oh = tid / 7, ow = tid - oh * 7;
        const float* wb = w + co * 128;
        for (int ci = 0; ci < 128; ci++)
            acc += wb[ci] * g_pool2[(b * 128 + ci) * 196 + (2 * oh) * 14 + 2 * ow];
        g_rs[(b * 256 + co) * 49 + tid] = acc;
    }
    float s = (tid < 49) ? acc : 0.f, q = s * s;
    for (int o = 16; o; o >>= 1) {
        s += __shfl_down_sync(0xffffffffu, s, o);
        q += __shfl_down_sync(0xffffffffu, q, o);
    }
    __shared__ float s_s[2], s_q[2];
    if ((tid & 31) == 0) { s_s[tid >> 5] = s; s_q[tid >> 5] = q; }
    __syncthreads();
    if (tid == 0) {
        atomicAdd(&g_sums[co], s_s[0] + s_s[1]);
        atomicAdd(&g_sqs[co], s_q[0] + s_q[1]);
    }
}

// y[b,c] = mean_p relu( bn(rc2) + bn(rs) )
__global__ void k_resfinal() {
    int idx = blockIdx.x * 256 + threadIdx.x;
    if (idx >= BB * 256) return;
    int b = idx >> 8, c = idx & 255;
    float sc2 = g_scr2[c], sh2 = g_shr2[c], scs = g_scs[c], shs = g_shs[c];
    const float* p2 = g_rc2 + (b * 256 + c) * 49;
    const float* ps = g_rs + (b * 256 + c) * 49;
    float s = 0.f;
    for (int p = 0; p < 49; p++) {
        float v = p2[p] * sc2 + sh2 + ps[p] * scs + shs;
        s += fmaxf(v, 0.f);
    }
    g_y[idx] = s * (1.f / 49.f);
}

// ---------------------------------------------------------------------------
// Tail fold: M = fc_w @ wo @ wv ; b2 = fc_w @ bo + fc_b ; out = y M^T + b2
// (softmax attention is identity: sum_k softmax = 1)
// ---------------------------------------------------------------------------
__global__ void k_foldT(const float* __restrict__ fcw, const float* __restrict__ wo) {
    int idx = blockIdx.x * 256 + threadIdx.x;
    if (idx >= 50 * 1024) return;
    int i = idx / 1024, j = idx - i * 1024;
    float s = 0.f;
    for (int c = 0; c < 256; c++) s += fcw[i * 256 + c] * wo[c * 1024 + j];
    g_T[idx] = s;
}

__global__ void k_foldM(const float* __restrict__ wv) {
    int idx = blockIdx.x * 256 + threadIdx.x;
    if (idx >= 50 * 256) return;
    int i = idx / 256, c = idx - i * 256;
    float s = 0.f;
    for (int j = 0; j < 1024; j++) s += g_T[i * 1024 + j] * wv[j * 256 + c];
    g_M[idx] = s;
}

__global__ void k_foldb(const float* __restrict__ fcw, const float* __restrict__ bo,
                        const float* __restrict__ fcb) {
    int i = threadIdx.x;
    if (i >= 50) return;
    float s = 0.f;
    for (int c = 0; c < 256; c++) s += fcw[i * 256 + c] * bo[c];
    g_b2[i] = s + fcb[i];
}

__global__ void k_final(float* __restrict__ out) {
    int idx = blockIdx.x * 64 + threadIdx.x;
    if (idx >= BB * 50) return;
    int b = idx / 50, i = idx - b * 50;
    float s = g_b2[i];
    for (int c = 0; c < 256; c++) s += g_y[b * 256 + c] * g_M[i * 256 + c];
    out[idx] = s;
}

// ---------------------------------------------------------------------------
// Launch
// ---------------------------------------------------------------------------
extern "C" void kernel_launch(void* const* d_in, const int* in_sizes, int n_in,
                              void* d_out, int out_size) {
    const float* imgs   = (const float*)d_in[0];
    const float* a1f1   = (const float*)d_in[1];
    const float* a1f2   = (const float*)d_in[2];
    const float* a1f2b  = (const float*)d_in[3];
    const float* dy1    = (const float*)d_in[4];
    const float* bn1g   = (const float*)d_in[5];
    const float* bn1b   = (const float*)d_in[6];
    const float* a2f1   = (const float*)d_in[7];
    const float* a2f2   = (const float*)d_in[8];
    const float* a2f2b  = (const float*)d_in[9];
    const float* dy2    = (const float*)d_in[10];
    const float* bn2g   = (const float*)d_in[11];
    const float* bn2b   = (const float*)d_in[12];
    const float* rc1w   = (const float*)d_in[13];
    const float* rbn1g  = (const float*)d_in[14];
    const float* rbn1b  = (const float*)d_in[15];
    const float* rc2w   = (const float*)d_in[16];
    const float* rbn2g  = (const float*)d_in[17];
    const float* rbn2b  = (const float*)d_in[18];
    const float* rsw    = (const float*)d_in[19];
    const float* rbnsg  = (const float*)d_in[20];
    const float* rbnsb  = (const float*)d_in[21];
    // d_in[22] = wq, d_in[23] = wk : unused (softmax attention is identity)
    const float* wv     = (const float*)d_in[24];
    const float* wo     = (const float*)d_in[25];
    const float* bo     = (const float*)d_in[26];
    const float* fcw    = (const float*)d_in[27];
    const float* fcb    = (const float*)d_in[28];
    float* out = (float*)d_out;
    (void)in_sizes; (void)n_in; (void)out_size;

    k_zero<<<16, 256>>>();
    // tail fold (independent)
    k_foldT<<<200, 256>>>(fcw, wo);
    k_foldM<<<50, 256>>>(wv);
    k_foldb<<<1, 64>>>(fcw, bo, fcb);

    // stage 1
    k_pooled1<<<192, 256>>>(imgs);
    k_attn1<<<1, 64>>>(a1f1, a1f2, a1f2b);
    k_w1agg<<<(BB * 9408 + 255) / 256, 256>>>(dy1);
    k_conv1<<<dim3(49, 16, BB), dim3(16, 16)>>>(imgs);
    k_bnscale<<<1, 64>>>(bn1g, bn1b, 802816.f, 0, 64);
    k_bnpool1<<<dim3(13, 64, BB), 256>>>();

    // stage 2
    k_attn2<<<1, 64>>>(a2f1, a2f2, a2f2b);
    k_w2agg<<<(BB * 73728 + 255) / 256, 256>>>(dy2);
    k_conv2<<<dim3(32, BB), 256>>>();
    k_bnscale<<<1, 128>>>(bn2g, bn2b, 50176.f, 1, 128);
    k_bnpool2<<<dim3(128, BB), 196>>>();

    // residual block
    k_resconv1<<<dim3(256, BB), 64>>>(rc1w);
    k_bnscale<<<1, 256>>>(rbn1g, rbn1b, 3136.f, 2, 256);
    k_bnrelu_rc1<<<(BB * 256 * 49 + 255) / 256, 256>>>();
    k_resconv2<<<dim3(256, BB), 64>>>(rc2w);
    k_shortcut<<<dim3(256, BB), 64>>>(rsw);
    k_bnscale<<<1, 256>>>(rbn2g, rbn2b, 3136.f, 3, 256);
    k_bnscale<<<1, 256>>>(rbnsg, rbnsb, 3136.f, 4, 256);
    k_resfinal<<<64, 256>>>();

    // tail
    k_final<<<50, 64>>>(out);
}

// round 2
// speedup vs baseline: 1.9056x; 1.9056x over previous
#include <cuda_runtime.h>
#include <math.h>

#define BB 64

// ---------------------------------------------------------------------------
// Scratch
// ---------------------------------------------------------------------------
__device__ float g_pooled1[BB * 3];
__device__ float g_attn1[BB * 8];
__device__ float g_w1[BB * 64 * 3 * 49];
__device__ float g_conv1[BB * 64 * 112 * 112];
__device__ float g_pool1[BB * 64 * 56 * 56];
__device__ float g_pooled2[BB * 64];
__device__ float g_attn2[BB * 8];
__device__ float g_w2[BB * 128 * 64 * 9];
__device__ float g_conv2[BB * 128 * 28 * 28];
__device__ float g_pool2[BB * 128 * 14 * 14];
__device__ float g_rc1[BB * 256 * 49];
__device__ float g_rc2[BB * 256 * 49];
__device__ float g_rs[BB * 256 * 49];
__device__ float g_y[BB * 256];

__device__ float g_sum1[64],  g_sq1[64],  g_sc1[64],  g_sh1[64];
__device__ float g_sum2[128], g_sq2[128], g_sc2[128], g_sh2[128];
__device__ float g_sumr1[256], g_sqr1[256], g_scr1[256], g_shr1[256];
__device__ float g_sumr2[256], g_sqr2[256], g_scr2[256], g_shr2[256];
__device__ float g_sums[256],  g_sqs[256],  g_scs[256],  g_shs[256];

__device__ float g_T[50 * 1024];
__device__ float g_M[50 * 256];
__device__ float g_b2[50];

// ---------------------------------------------------------------------------
// Utilities
// ---------------------------------------------------------------------------
__global__ void k_zero() {
    int i = blockIdx.x * blockDim.x + threadIdx.x;
    if (i < 64)  { g_sum1[i] = 0.f; g_sq1[i] = 0.f; }
    if (i < 128) { g_sum2[i] = 0.f; g_sq2[i] = 0.f; }
    if (i < 256) { g_sums[i] = 0.f; g_sqs[i] = 0.f; }
    if (i < BB * 64) g_pooled2[i] = 0.f;
}

// stage: 0=bn1 1=bn2 2=res_bn1 3=res_bn2 4=res_bns
__global__ void k_bnscale(const float* __restrict__ g, const float* __restrict__ be,
                          float cnt, int stage, int C) {
    int c = blockIdx.x * blockDim.x + threadIdx.x;
    if (c >= C) return;
    float *su, *sq, *sc, *sh;
    switch (stage) {
        case 0:  su = g_sum1;  sq = g_sq1;  sc = g_sc1;  sh = g_sh1;  break;
        case 1:  su = g_sum2;  sq = g_sq2;  sc = g_sc2;  sh = g_sh2;  break;
        case 2:  su = g_sumr1; sq = g_sqr1; sc = g_scr1; sh = g_shr1; break;
        case 3:  su = g_sumr2; sq = g_sqr2; sc = g_scr2; sh = g_shr2; break;
        default: su = g_sums;  sq = g_sqs;  sc = g_scs;  sh = g_shs;  break;
    }
    float m = su[c] / cnt;
    float v = sq[c] / cnt - m * m;
    float s = g[c] * rsqrtf(v + 1e-5f);
    sc[c] = s;
    sh[c] = be[c] - m * s;
}

// per-channel stats of a [B,256,49] tensor; which: 0 -> rc1, 1 -> rc2
__global__ void k_chstats(int which) {
    const float* src = which ? g_rc2 : g_rc1;
    float* su = which ? g_sumr2 : g_sumr1;
    float* sq = which ? g_sqr2 : g_sqr1;
    int c = blockIdx.x;
    float s = 0.f, q = 0.f;
    for (int t = threadIdx.x; t < BB * 49; t += 128) {
        int b = t / 49, p = t - b * 49;
        float v = src[(b * 256 + c) * 49 + p];
        s += v; q += v * v;
    }
    for (int o = 16; o; o >>= 1) {
        s += __shfl_down_sync(0xffffffffu, s, o);
        q += __shfl_down_sync(0xffffffffu, q, o);
    }
    __shared__ float rs[4], rq[4];
    int w = threadIdx.x >> 5;
    if ((threadIdx.x & 31) == 0) { rs[w] = s; rq[w] = q; }
    __syncthreads();
    if (threadIdx.x == 0) {
        su[c] = rs[0] + rs[1] + rs[2] + rs[3];
        sq[c] = rq[0] + rq[1] + rq[2] + rq[3];
    }
}

// ---------------------------------------------------------------------------
// Stage-1 attention
// ---------------------------------------------------------------------------
__global__ void k_pooled1(const float* __restrict__ imgs) {
    int bc = blockIdx.x;
    int tid = threadIdx.x;
    const float* p = imgs + (long)bc * 50176;
    float s = 0.f;
    for (int i = tid; i < 50176; i += 256) s += p[i];
    __shared__ float red[256];
    red[tid] = s; __syncthreads();
    for (int o = 128; o; o >>= 1) { if (tid < o) red[tid] += red[tid + o]; __syncthreads(); }
    if (tid == 0) g_pooled1[bc] = red[0] * (1.f / 50176.f);
}

__global__ void k_attn1(const float* __restrict__ fc1, const float* __restrict__ fc2,
                        const float* __restrict__ fc2b) {
    int b = threadIdx.x;
    if (b >= BB) return;
    float p[3];
    for (int c = 0; c < 3; c++) p[c] = g_pooled1[b * 3 + c];
    float h[8];
    for (int j = 0; j < 8; j++) {
        float s = 0.f;
        for (int c = 0; c < 3; c++) s += p[c] * fc1[j * 3 + c];
        h[j] = fmaxf(s, 0.f);
    }
    float lg[8], mx = -1e30f;
    for (int k = 0; k < 8; k++) {
        float s = fc2b[k];
        for (int j = 0; j < 8; j++) s += h[j] * fc2[k * 8 + j];
        lg[k] = s; mx = fmaxf(mx, s);
    }
    float den = 0.f;
    for (int k = 0; k < 8; k++) { lg[k] = expf(lg[k] - mx); den += lg[k]; }
    float inv = 1.f / den;
    for (int k = 0; k < 8; k++) g_attn1[b * 8 + k] = lg[k] * inv;
}

__global__ void k_w1agg(const float* __restrict__ dy1) {
    int idx = blockIdx.x * 256 + threadIdx.x;
    if (idx >= BB * 9408) return;
    int b = idx / 9408, i = idx - b * 9408;
    float s = 0.f;
#pragma unroll
    for (int k = 0; k < 8; k++) s += g_attn1[b * 8 + k] * dy1[k * 9408 + i];
    g_w1[idx] = s;
}

// ---------------------------------------------------------------------------
// Conv1: 3->64, 7x7 s2 p3. Thread = 1 ow x 4 oh x 8 co. Tile 28w x 16h.
// grid (28 tiles, 8 cog, 64 b), block 128 (112 active)
// ---------------------------------------------------------------------------
__global__ void k_conv1(const float* __restrict__ imgs) {
    __shared__ float s_in[3 * 37 * 62];   // rows 37, pitch 62
    __shared__ float s_w[8 * 147];
    __shared__ float s_stat[16];
    int b = blockIdx.z, cog = blockIdx.y;
    int tr = blockIdx.x >> 2, tc = blockIdx.x & 3;
    int oh0 = tr * 16, ow0 = tc * 28;
    int tid = threadIdx.x;

    for (int t = tid; t < 1176; t += 128)
        s_w[t] = g_w1[b * 9408 + cog * 1176 + t];
    int ih0 = 2 * oh0 - 3, iw0 = 2 * ow0 - 3;
    for (int t = tid; t < 6882; t += 128) {
        int ci = t / 2294, rem = t - ci * 2294;
        int r = rem / 62, c = rem - r * 62;
        int ih = ih0 + r, iw = iw0 + c;
        float v = 0.f;
        if ((unsigned)ih < 224u && (unsigned)iw < 224u)
            v = imgs[((b * 3 + ci) * 224 + ih) * 224 + iw];
        s_in[t] = v;
    }
    if (tid < 16) s_stat[tid] = 0.f;
    __syncthreads();

    float acc[4][8];
#pragma unroll
    for (int j = 0; j < 4; j++)
#pragma unroll
        for (int co = 0; co < 8; co++) acc[j][co] = 0.f;

    int tx = tid % 28, ty = tid / 28;   // ty 0..3 active (tid<112)
    if (tid < 112) {
        for (int ci = 0; ci < 3; ci++) {
            for (int kh = 0; kh < 7; kh++) {
                int rbase = ci * 2294 + (8 * ty + kh) * 62 + 2 * tx;
#pragma unroll
                for (int kw = 0; kw < 7; kw++) {
                    float i0 = s_in[rbase + kw];
                    float i1 = s_in[rbase + kw + 124];
                    float i2 = s_in[rbase + kw + 248];
                    float i3 = s_in[rbase + kw + 372];
                    const float* wp = s_w + ci * 49 + kh * 7 + kw;
#pragma unroll
                    for (int co = 0; co < 8; co++) {
                        float w = wp[co * 147];
                        acc[0][co] += w * i0;
                        acc[1][co] += w * i1;
                        acc[2][co] += w * i2;
                        acc[3][co] += w * i3;
                    }
                }
            }
        }
#pragma unroll
        for (int co = 0; co < 8; co++) {
            long cb = ((long)(b * 64 + cog * 8 + co)) * 12544;
#pragma unroll
            for (int j = 0; j < 4; j++) {
                int oh = oh0 + 4 * ty + j;
                g_conv1[cb + oh * 112 + ow0 + tx] = acc[j][co];
            }
        }
    }
    // stats
#pragma unroll
    for (int co = 0; co < 8; co++) {
        float s = acc[0][co] + acc[1][co] + acc[2][co] + acc[3][co];
        float q = acc[0][co] * acc[0][co] + acc[1][co] * acc[1][co]
                + acc[2][co] * acc[2][co] + acc[3][co] * acc[3][co];
        for (int o = 16; o; o >>= 1) {
            s += __shfl_down_sync(0xffffffffu, s, o);
            q += __shfl_down_sync(0xffffffffu, q, o);
        }
        if ((tid & 31) == 0) { atomicAdd(&s_stat[co], s); atomicAdd(&s_stat[8 + co], q); }
    }
    __syncthreads();
    if (tid < 8) {
        atomicAdd(&g_sum1[cog * 8 + tid], s_stat[tid]);
        atomicAdd(&g_sq1[cog * 8 + tid], s_stat[8 + tid]);
    }
}

// ---------------------------------------------------------------------------
// BN1 + maxpool3 s2 p1: 112->56, accumulate pooled2
// ---------------------------------------------------------------------------
__global__ void k_bnpool1() {
    int b = blockIdx.z, c = blockIdx.y;
    int p = blockIdx.x * 256 + threadIdx.x;
    float outv = 0.f;
    bool valid = (p < 3136);
    if (valid) {
        int oh = p / 56, ow = p - oh * 56;
        float sc = g_sc1[c], sh = g_sh1[c];
        const float* ip = g_conv1 + (long)(b * 64 + c) * 12544;
        float m = -1e30f;
#pragma unroll
        for (int r = 0; r < 3; r++) {
            int ih = 2 * oh - 1 + r;
            if ((unsigned)ih >= 112u) continue;
#pragma unroll
            for (int cc = 0; cc < 3; cc++) {
                int iw = 2 * ow - 1 + cc;
                if ((unsigned)iw >= 112u) continue;
                m = fmaxf(m, ip[ih * 112 + iw] * sc + sh);
            }
        }
        g_pool1[(b * 64 + c) * 3136 + p] = m;
        outv = m;
    }
    float s = valid ? outv : 0.f;
    for (int o = 16; o; o >>= 1) s += __shfl_down_sync(0xffffffffu, s, o);
    __shared__ float s_red;
    if (threadIdx.x == 0) s_red = 0.f;
    __syncthreads();
    if ((threadIdx.x & 31) == 0) atomicAdd(&s_red, s);
    __syncthreads();
    if (threadIdx.x == 0) atomicAdd(&g_pooled2[b * 64 + c], s_red);
}

// ---------------------------------------------------------------------------
// Stage-2 attention
// ---------------------------------------------------------------------------
__global__ void k_attn2(const float* __restrict__ fc1, const float* __restrict__ fc2,
                        const float* __restrict__ fc2b) {
    int b = threadIdx.x;
    if (b >= BB) return;
    float h[17];
    for (int j = 0; j < 17; j++) {
        float s = 0.f;
        for (int c = 0; c < 64; c++)
            s += (g_pooled2[b * 64 + c] * (1.f / 3136.f)) * fc1[j * 64 + c];
        h[j] = fmaxf(s, 0.f);
    }
    float lg[8], mx = -1e30f;
    for (int k = 0; k < 8; k++) {
        float s = fc2b[k];
        for (int j = 0; j < 17; j++) s += h[j] * fc2[k * 17 + j];
        lg[k] = s; mx = fmaxf(mx, s);
    }
    float den = 0.f;
    for (int k = 0; k < 8; k++) { lg[k] = expf(lg[k] - mx); den += lg[k]; }
    float inv = 1.f / den;
    for (int k = 0; k < 8; k++) g_attn2[b * 8 + k] = lg[k] * inv;
}

__global__ void k_w2agg(const float* __restrict__ dy2) {
    int idx = blockIdx.x * 256 + threadIdx.x;
    if (idx >= BB * 73728) return;
    int b = idx / 73728, i = idx - b * 73728;
    float s = 0.f;
#pragma unroll
    for (int k = 0; k < 8; k++) s += g_attn2[b * 8 + k] * dy2[k * 73728 + i];
    g_w2[idx] = s;
}

// ---------------------------------------------------------------------------
// Conv2: 64->128, 3x3 s2 p1: 56->28. Thread = 1 ow x 4 oh x 8 co.
// grid (16 cog, 64 b), block 224 (196 active), ci chunks of 2 (padded plane 58x58)
// ---------------------------------------------------------------------------
__global__ void k_conv2() {
    __shared__ float s_in[2 * 3364];    // 2 x 58x58 padded
    __shared__ float s_w[144];          // 8co x 2ci x 9
    __shared__ float s_stat[16];
    int b = blockIdx.y, cog = blockIdx.x;
    int tid = threadIdx.x;
    int tx = tid % 28, tyq = tid / 28;  // tyq 0..6 active

    for (int t = tid; t < 2 * 3364; t += 224) s_in[t] = 0.f;
    if (tid < 16) s_stat[tid] = 0.f;
    __syncthreads();

    float acc[4][8];
#pragma unroll
    for (int j = 0; j < 4; j++)
#pragma unroll
        for (int co = 0; co < 8; co++) acc[j][co] = 0.f;

    for (int c0 = 0; c0 < 64; c0 += 2) {
        for (int t = tid; t < 2 * 3136; t += 224) {
            int ci = t / 3136, p = t - ci * 3136;
            int r = p / 56, c = p - r * 56;
            s_in[ci * 3364 + (r + 1) * 58 + (c + 1)] =
                g_pool1[(b * 64 + c0 + ci) * 3136 + p];
        }
        if (tid < 144) {
            int co = tid / 18, rem = tid - co * 18;
            int cil = rem / 9, k = rem - cil * 9;
            s_w[tid] = g_w2[b * 73728 + (cog * 8 + co) * 576 + (c0 + cil) * 9 + k];
        }
        __syncthreads();
        if (tid < 196) {
#pragma unroll
            for (int ci = 0; ci < 2; ci++) {
#pragma unroll
                for (int kh = 0; kh < 3; kh++) {
                    int rbase = ci * 3364 + (8 * tyq + kh) * 58 + 2 * tx;
#pragma unroll
                    for (int kw = 0; kw < 3; kw++) {
                        float i0 = s_in[rbase + kw];
                        float i1 = s_in[rbase + kw + 116];
                        float i2 = s_in[rbase + kw + 232];
                        float i3 = s_in[rbase + kw + 348];
                        const float* wp = s_w + ci * 9 + kh * 3 + kw;
#pragma unroll
                        for (int co = 0; co < 8; co++) {
                            float w = wp[co * 18];
                            acc[0][co] += w * i0;
                            acc[1][co] += w * i1;
                            acc[2][co] += w * i2;
                            acc[3][co] += w * i3;
                        }
                    }
                }
            }
        }
        __syncthreads();
    }

    if (tid < 196) {
#pragma unroll
        for (int co = 0; co < 8; co++) {
            int cb = (b * 128 + cog * 8 + co) * 784;
#pragma unroll
            for (int j = 0; j < 4; j++) {
                int oh = 4 * tyq + j;
                g_conv2[cb + oh * 28 + tx] = acc[j][co];
            }
        }
    }
#pragma unroll
    for (int co = 0; co < 8; co++) {
        float s = acc[0][co] + acc[1][co] + acc[2][co] + acc[3][co];
        float q = acc[0][co] * acc[0][co] + acc[1][co] * acc[1][co]
                + acc[2][co] * acc[2][co] + acc[3][co] * acc[3][co];
        for (int o = 16; o; o >>= 1) {
            s += __shfl_down_sync(0xffffffffu, s, o);
            q += __shfl_down_sync(0xffffffffu, q, o);
        }
        if ((tid & 31) == 0) { atomicAdd(&s_stat[co], s); atomicAdd(&s_stat[8 + co], q); }
    }
    __syncthreads();
    if (tid < 8) {
        atomicAdd(&g_sum2[cog * 8 + tid], s_stat[tid]);
        atomicAdd(&g_sq2[cog * 8 + tid], s_stat[8 + tid]);
    }
}

// ---------------------------------------------------------------------------
// BN2 + maxpool3 s2 p1: 28->14
// ---------------------------------------------------------------------------
__global__ void k_bnpool2() {
    int b = blockIdx.y, c = blockIdx.x;
    int p = threadIdx.x;
    if (p >= 196) return;
    int oh = p / 14, ow = p - oh * 14;
    float sc = g_sc2[c], sh = g_sh2[c];
    const float* ip = g_conv2 + (b * 128 + c) * 784;
    float m = -1e30f;
#pragma unroll
    for (int r = 0; r < 3; r++) {
        int ih = 2 * oh - 1 + r;
        if ((unsigned)ih >= 28u) continue;
#pragma unroll
        for (int cc = 0; cc < 3; cc++) {
            int iw = 2 * ow - 1 + cc;
            if ((unsigned)iw >= 28u) continue;
            m = fmaxf(m, ip[ih * 28 + iw] * sc + sh);
        }
    }
    g_pool2[(b * 128 + c) * 196 + p] = m;
}

// ---------------------------------------------------------------------------
// resconv1: 128->256 3x3 s2, 14x14 -> 7x7. grid (8 cog, 64 b), block 196.
// thread = (px 49, yq 4) x 8 co; ci chunks of 8; padded plane 15x18.
// ---------------------------------------------------------------------------
__global__ void k_resconv1(const float* __restrict__ w) {
    __shared__ float s_in[8 * 270];
    __shared__ float s_w[2304];         // 32co x 8ci x 9
    int b = blockIdx.y, cog = blockIdx.x;
    int tid = threadIdx.x;
    int px = tid % 49, yq = tid / 49;
    int oh = px / 7, ow = px - oh * 7;
    float acc[8];
#pragma unroll
    for (int i = 0; i < 8; i++) acc[i] = 0.f;

    for (int c0 = 0; c0 < 128; c0 += 8) {
        for (int t = tid; t < 2160; t += 196) {
            int ci = t / 270, rem = t - ci * 270;
            int r = rem / 18, c = rem - r * 18;
            int ih = r - 1, iw = c - 1;
            float v = 0.f;
            if ((unsigned)ih < 14u && (unsigned)iw < 14u)
                v = g_pool2[(b * 128 + c0 + ci) * 196 + ih * 14 + iw];
            s_in[t] = v;
        }
        for (int t = tid; t < 2304; t += 196) {
            int co = t / 72, rem = t - co * 72;
            int ci = rem / 9, k = rem - ci * 9;
            s_w[t] = w[(cog * 32 + co) * 1152 + (c0 + ci) * 9 + k];
        }
        __syncthreads();
#pragma unroll
        for (int ci = 0; ci < 8; ci++) {
#pragma unroll
            for (int kh = 0; kh < 3; kh++) {
                int base = ci * 270 + (2 * oh + kh) * 18 + 2 * ow;
#pragma unroll
                for (int kw = 0; kw < 3; kw++) {
                    float v = s_in[base + kw];
                    const float* wp = s_w + (yq * 8) * 72 + ci * 9 + kh * 3 + kw;
#pragma unroll
                    for (int co = 0; co < 8; co++)
                        acc[co] += wp[co * 72] * v;
                }
            }
        }
        __syncthreads();
    }
#pragma unroll
    for (int co = 0; co < 8; co++)
        g_rc1[(b * 256 + cog * 32 + yq * 8 + co) * 49 + px] = acc[co];
}

// ---------------------------------------------------------------------------
// resconv2: 256->256 3x3 s1, 7x7. bn+relu of rc1 fused into staging.
// grid (8 cog, 64 b), block 196; ci chunks of 8; padded plane 9x12.
// ---------------------------------------------------------------------------
__global__ void k_resconv2(const float* __restrict__ w) {
    __shared__ float s_in[8 * 108];
    __shared__ float s_w[2304];
    int b = blockIdx.y, cog = blockIdx.x;
    int tid = threadIdx.x;
    int px = tid % 49, yq = tid / 49;
    int oh = px / 7, ow = px - oh * 7;
    float acc[8];
#pragma unroll
    for (int i = 0; i < 8; i++) acc[i] = 0.f;

    for (int c0 = 0; c0 < 256; c0 += 8) {
        for (int t = tid; t < 864; t += 196) {
            int ci = t / 108, rem = t - ci * 108;
            int r = rem / 12, c = rem - r * 12;
            int ih = r - 1, iw = c - 1;
            float v = 0.f;
            if ((unsigned)ih < 7u && (unsigned)iw < 7u) {
                float sc = g_scr1[c0 + ci], sh = g_shr1[c0 + ci];
                v = fmaxf(g_rc1[(b * 256 + c0 + ci) * 49 + ih * 7 + iw] * sc + sh, 0.f);
            }
            s_in[t] = v;
        }
        for (int t = tid; t < 2304; t += 196) {
            int co = t / 72, rem = t - co * 72;
            int ci = rem / 9, k = rem - ci * 9;
            s_w[t] = w[(cog * 32 + co) * 2304 + (c0 + ci) * 9 + k];
        }
        __syncthreads();
#pragma unroll
        for (int ci = 0; ci < 8; ci++) {
#pragma unroll
            for (int kh = 0; kh < 3; kh++) {
                int base = ci * 108 + (oh + kh) * 12 + ow;
#pragma unroll
                for (int kw = 0; kw < 3; kw++) {
                    float v = s_in[base + kw];
                    const float* wp = s_w + (yq * 8) * 72 + ci * 9 + kh * 3 + kw;
#pragma unroll
                    for (int co = 0; co < 8; co++)
                        acc[co] += wp[co * 72] * v;
                }
            }
        }
        __syncthreads();
    }
#pragma unroll
    for (int co = 0; co < 8; co++)
        g_rc2[(b * 256 + cog * 32 + yq * 8 + co) * 49 + px] = acc[co];
}

// ---------------------------------------------------------------------------
// shortcut 1x1 s2 (with inline stats)
// ---------------------------------------------------------------------------
__global__ void k_shortcut(const float* __restrict__ w) {
    int b = blockIdx.y, co = blockIdx.x;
    int tid = threadIdx.x;
    float acc = 0.f;
    if (tid < 49) {
        int oh = tid / 7, ow = tid - oh * 7;
        const float* wb = w + co * 128;
        for (int ci = 0; ci < 128; ci++)
            acc += wb[ci] * g_pool2[(b * 128 + ci) * 196 + (2 * oh) * 14 + 2 * ow];
        g_rs[(b * 256 + co) * 49 + tid] = acc;
    }
    float s = (tid < 49) ? acc : 0.f, q = s * s;
    for (int o = 16; o; o >>= 1) {
        s += __shfl_down_sync(0xffffffffu, s, o);
        q += __shfl_down_sync(0xffffffffu, q, o);
    }
    __shared__ float s_s[2], s_q[2];
    if ((tid & 31) == 0) { s_s[tid >> 5] = s; s_q[tid >> 5] = q; }
    __syncthreads();
    if (tid == 0) {
        atomicAdd(&g_sums[co], s_s[0] + s_s[1]);
        atomicAdd(&g_sqs[co], s_q[0] + s_q[1]);
    }
}

__global__ void k_resfinal() {
    int idx = blockIdx.x * 256 + threadIdx.x;
    if (idx >= BB * 256) return;
    int b = idx >> 8, c = idx & 255;
    float sc2 = g_scr2[c], sh2 = g_shr2[c], scs = g_scs[c], shs = g_shs[c];
    const float* p2 = g_rc2 + (b * 256 + c) * 49;
    const float* ps = g_rs + (b * 256 + c) * 49;
    float s = 0.f;
    for (int p = 0; p < 49; p++) {
        float v = p2[p] * sc2 + sh2 + ps[p] * scs + shs;
        s += fmaxf(v, 0.f);
    }
    g_y[idx] = s * (1.f / 49.f);
}

// ---------------------------------------------------------------------------
// Tail fold (softmax attention collapses to 1x1 conv: wo@wv)
// ---------------------------------------------------------------------------
__global__ void k_foldT(const float* __restrict__ fcw, const float* __restrict__ wo) {
    int idx = blockIdx.x * 256 + threadIdx.x;
    if (idx >= 50 * 1024) return;
    int i = idx / 1024, j = idx - i * 1024;
    float s = 0.f;
    for (int c = 0; c < 256; c++) s += fcw[i * 256 + c] * wo[c * 1024 + j];
    g_T[idx] = s;
}

__global__ void k_foldM(const float* __restrict__ wv) {
    int idx = blockIdx.x * 256 + threadIdx.x;
    if (idx >= 50 * 256) return;
    int i = idx / 256, c = idx - i * 256;
    float s = 0.f;
    for (int j = 0; j < 1024; j++) s += g_T[i * 1024 + j] * wv[j * 256 + c];
    g_M[idx] = s;
}

__global__ void k_foldb(const float* __restrict__ fcw, const float* __restrict__ bo,
                        const float* __restrict__ fcb) {
    int i = threadIdx.x;
    if (i >= 50) return;
    float s = 0.f;
    for (int c = 0; c < 256; c++) s += fcw[i * 256 + c] * bo[c];
    g_b2[i] = s + fcb[i];
}

__global__ void k_final(float* __restrict__ out) {
    int idx = blockIdx.x * 64 + threadIdx.x;
    if (idx >= BB * 50) return;
    int b = idx / 50, i = idx - b * 50;
    float s = g_b2[i];
    for (int c = 0; c < 256; c++) s += g_y[b * 256 + c] * g_M[i * 256 + c];
    out[idx] = s;
}

// ---------------------------------------------------------------------------
// Launch
// ---------------------------------------------------------------------------
extern "C" void kernel_launch(void* const* d_in, const int* in_sizes, int n_in,
                              void* d_out, int out_size) {
    const float* imgs   = (const float*)d_in[0];
    const float* a1f1   = (const float*)d_in[1];
    const float* a1f2   = (const float*)d_in[2];
    const float* a1f2b  = (const float*)d_in[3];
    const float* dy1    = (const float*)d_in[4];
    const float* bn1g   = (const float*)d_in[5];
    const float* bn1b   = (const float*)d_in[6];
    const float* a2f1   = (const float*)d_in[7];
    const float* a2f2   = (const float*)d_in[8];
    const float* a2f2b  = (const float*)d_in[9];
    const float* dy2    = (const float*)d_in[10];
    const float* bn2g   = (const float*)d_in[11];
    const float* bn2b   = (const float*)d_in[12];
    const float* rc1w   = (const float*)d_in[13];
    const float* rbn1g  = (const float*)d_in[14];
    const float* rbn1b  = (const float*)d_in[15];
    const float* rc2w   = (const float*)d_in[16];
    const float* rbn2g  = (const float*)d_in[17];
    const float* rbn2b  = (const float*)d_in[18];
    const float* rsw    = (const float*)d_in[19];
    const float* rbnsg  = (const float*)d_in[20];
    const float* rbnsb  = (const float*)d_in[21];
    const float* wv     = (const float*)d_in[24];
    const float* wo     = (const float*)d_in[25];
    const float* bo     = (const float*)d_in[26];
    const float* fcw    = (const float*)d_in[27];
    const float* fcb    = (const float*)d_in[28];
    float* out = (float*)d_out;
    (void)in_sizes; (void)n_in; (void)out_size;

    k_zero<<<16, 256>>>();
    k_foldT<<<200, 256>>>(fcw, wo);
    k_foldM<<<50, 256>>>(wv);
    k_foldb<<<1, 64>>>(fcw, bo, fcb);

    // stage 1
    k_pooled1<<<192, 256>>>(imgs);
    k_attn1<<<1, 64>>>(a1f1, a1f2, a1f2b);
    k_w1agg<<<(BB * 9408 + 255) / 256, 256>>>(dy1);
    k_conv1<<<dim3(28, 8, BB), 128>>>(imgs);
    k_bnscale<<<1, 64>>>(bn1g, bn1b, 802816.f, 0, 64);
    k_bnpool1<<<dim3(13, 64, BB), 256>>>();

    // stage 2
    k_attn2<<<1, 64>>>(a2f1, a2f2, a2f2b);
    k_w2agg<<<(BB * 73728 + 255) / 256, 256>>>(dy2);
    k_conv2<<<dim3(16, BB), 224>>>();
    k_bnscale<<<1, 128>>>(bn2g, bn2b, 50176.f, 1, 128);
    k_bnpool2<<<dim3(128, BB), 196>>>();

    // residual block
    k_resconv1<<<dim3(8, BB), 196>>>(rc1w);
    k_chstats<<<256, 128>>>(0);
    k_bnscale<<<1, 256>>>(rbn1g, rbn1b, 3136.f, 2, 256);
    k_resconv2<<<dim3(8, BB), 196>>>(rc2w);
    k_chstats<<<256, 128>>>(1);
    k_shortcut<<<dim3(256, BB), 64>>>(rsw);
    k_bnscale<<<1, 256>>>(rbn2g, rbn2b, 3136.f, 3, 256);
    k_bnscale<<<1, 256>>>(rbnsg, rbnsb, 3136.f, 4, 256);
    k_resfinal<<<64, 256>>>();

    k_final<<<50, 64>>>(out);
}